// round 14
// baseline (speedup 1.0000x reference)
#include <cuda_runtime.h>
#include <cstdint>
#include <cstddef>

#define NF 40
#define NE 64
#define NBATCH 4096
#define NP 780
#define NPH 390                 // pairs per CTA (half)
#define ROW_F4 (NP*16)          // 12480 float4 per full output row
#define HROW_F4 (NPH*16)        // 6240
#define X_F4 (NF*16)            // 640 float4 per x row
#define NWARP 13
#define NTH (NWARP*32)          // 416
#define PPW 30                  // pairs per warp = NPH/NWARP
#define ITERS 15                // per-thread iters (2 pairs per iter across warp)
#define BUFS 6
#define BUF_F4 128              // 4 iters * 32 lanes = 2 KB
#define WARP_F4 (PPW*16)        // 480 contiguous output float4 per warp per row

// dynamic smem: xs4[X_F4] | stage[NWARP][BUFS][BUF_F4]   (~166 KB, 1 CTA/SM)
#define SMEM_BYTES ((X_F4 + NWARP*BUFS*BUF_F4) * sizeof(float4))

__device__ __forceinline__ void bulk_store(const float4* gdst, uint32_t ssrc, int bytes) {
    asm volatile("cp.async.bulk.global.shared::cta.bulk_group [%0], [%1], %2;"
                 :: "l"(gdst), "r"(ssrc), "r"(bytes) : "memory");
}

__global__ __launch_bounds__(NTH, 1)
void ffm_kernel(const float* __restrict__ x,
                const float* __restrict__ fe,
                float* __restrict__ out) {
    extern __shared__ float4 sm4[];
    float4* xs4   = sm4;
    float4* stage = sm4 + X_F4;

    const int tid  = threadIdx.x;
    const int warp = tid >> 5;
    const int lane = tid & 31;
    const int word = lane & 15;
    const int sel  = lane >> 4;          // which of the 2 pairs in an iter

    const int half  = blockIdx.x & 1;
    const int pbase = half * NPH + warp * PPW;

    // ---- per-thread precompute: inter in registers + xs offsets ----
    float4  interReg[ITERS];
    unsigned offs[ITERS];                // (i_f4idx << 16) | j_f4idx into xs4
    {
        int i = 0, rem = pbase;
        while (rem >= NF - 1 - i) { rem -= NF - 1 - i; ++i; }
        int j = i + 1 + rem;
        int pi[PPW], pj[PPW];
        #pragma unroll
        for (int p = 0; p < PPW; ++p) {
            pi[p] = i; pj[p] = j;
            if (++j == NF) { ++i; j = i + 1; }
        }
        const float4* fe4 = (const float4*)fe;
        #pragma unroll
        for (int k = 0; k < ITERS; ++k) {
            int ii = pi[2*k + sel], jj = pj[2*k + sel];
            offs[k] = ((unsigned)(ii*16 + word) << 16) | (unsigned)(jj*16 + word);
            float4 a = fe4[(size_t)(ii*NF + jj)*16 + word];
            float4 b = fe4[(size_t)(jj*NF + ii)*16 + word];
            interReg[k] = make_float4(a.x*b.x, a.y*b.y, a.z*b.z, a.w*b.w);
        }
    }

    float4* mybufs = stage + (size_t)warp * (BUFS * BUF_F4);
    const uint32_t sbase = (uint32_t)__cvta_generic_to_shared(mybufs);

    // ---- persistent batch loop, register-prefetched x ----
    const float4* xg4 = (const float4*)x;
    const int b0      = blockIdx.x >> 1;
    const int bstride = gridDim.x >> 1;

    float4 r0 = make_float4(0.f,0.f,0.f,0.f), r1 = r0;
    if (b0 < NBATCH) {
        r0 = xg4[(size_t)b0 * X_F4 + tid];
        if (tid < X_F4 - NTH) r1 = xg4[(size_t)b0 * X_F4 + tid + NTH];
    }

    int bufsel = 0;   // cycles 0..BUFS-1 across all chunks, all rows

    for (int b = b0; b < NBATCH; b += bstride) {
        __syncthreads();                 // previous row's xs readers done
        xs4[tid] = r0;
        if (tid < X_F4 - NTH) xs4[tid + NTH] = r1;

        int bn = b + bstride;
        if (bn < NBATCH) {
            r0 = xg4[(size_t)bn * X_F4 + tid];
            if (tid < X_F4 - NTH) r1 = xg4[(size_t)bn * X_F4 + tid + NTH];
        }
        __syncthreads();                 // xs4 ready

        const float4* og4 = (const float4*)out + (size_t)b * ROW_F4
                          + (size_t)half * HROW_F4 + (size_t)warp * WARP_F4;

        #pragma unroll
        for (int c = 0; c < 4; ++c) {
            const int kbeg = c * 4;
            const int ksz  = (c < 3) ? 4 : 3;       // 4+4+4+3 = 15 iters

            // buffer reuse: allow up to BUFS-1 pending bulk groups
            if (lane == 0)
                asm volatile("cp.async.bulk.wait_group.read %0;" :: "n"(BUFS-1) : "memory");
            __syncwarp();

            float4* buf = mybufs + bufsel * BUF_F4;
            #pragma unroll
            for (int kk = 0; kk < 4; ++kk) {
                if (kk < ksz) {
                    const int k = kbeg + kk;
                    unsigned o  = offs[k];
                    float4 a  = xs4[o >> 16];
                    float4 cj = xs4[o & 0xffffu];
                    float4 t  = interReg[k];
                    buf[kk*32 + lane] = make_float4(a.x*cj.x*t.x,
                                                    a.y*cj.y*t.y,
                                                    a.z*cj.z*t.z,
                                                    a.w*cj.w*t.w);
                }
            }
            asm volatile("fence.proxy.async.shared::cta;" ::: "memory");
            __syncwarp();
            if (lane == 0) {
                bulk_store(og4 + kbeg*32,
                           sbase + (uint32_t)(bufsel * BUF_F4 * sizeof(float4)),
                           ksz * 32 * (int)sizeof(float4));
                asm volatile("cp.async.bulk.commit_group;" ::: "memory");
            }
            if (++bufsel == BUFS) bufsel = 0;
        }
    }

    // drain before exit
    if (lane == 0)
        asm volatile("cp.async.bulk.wait_group.read 0;" ::: "memory");
}

extern "C" void kernel_launch(void* const* d_in, const int* in_sizes, int n_in,
                              void* d_out, int out_size) {
    const float* x  = (const float*)d_in[0];   // [B, F, E] float32
    const float* fe = (const float*)d_in[1];   // [F, F, E] float32
    float* out = (float*)d_out;                // [B, P*E] float32

    (void)in_sizes; (void)n_in; (void)out_size;

    cudaFuncSetAttribute(ffm_kernel,
                         cudaFuncAttributeMaxDynamicSharedMemorySize,
                         (int)SMEM_BYTES);

    int dev = 0, sms = 148;
    cudaGetDevice(&dev);
    cudaDeviceGetAttribute(&sms, cudaDevAttrMultiProcessorCount, dev);
    int grid = sms & ~1;                       // even: 2 pair-halves, 1 CTA/SM
    if (grid < 2) grid = 2;

    ffm_kernel<<<grid, NTH, SMEM_BYTES>>>(x, fe, out);
}

// round 15
// speedup vs baseline: 1.0652x; 1.0652x over previous
#include <cuda_runtime.h>
#include <cstdint>
#include <cstddef>

#define NF 40
#define NE 64
#define NBATCH 4096
#define NP 780
#define NPH 390                 // pairs per CTA (half)
#define ROW_F4 (NP*16)          // 12480 float4 per full output row
#define HROW_F4 (NPH*16)        // 6240
#define X_F4 (NF*16)            // 640 float4 per x row
#define NWARP 13
#define NTH (NWARP*32)          // 416
#define PPW 30                  // pairs per warp = NPH/NWARP
#define ITERS 15                // per-thread iters (2 pairs per iter across warp)
#define BUFS 3
#define BUF_F4 128              // 4 iters * 32 lanes = 2 KB
#define WARP_F4 (PPW*16)        // 480 contiguous output float4 per warp per row

// dynamic smem: xs4[X_F4] | stage[NWARP][BUFS][BUF_F4]   (~88 KB, 1 CTA/SM)
#define SMEM_BYTES ((X_F4 + NWARP*BUFS*BUF_F4) * sizeof(float4))

__device__ __forceinline__ void bulk_store(const float4* gdst, uint32_t ssrc, int bytes) {
    asm volatile("cp.async.bulk.global.shared::cta.bulk_group [%0], [%1], %2;"
                 :: "l"(gdst), "r"(ssrc), "r"(bytes) : "memory");
}

__global__ __launch_bounds__(NTH, 1)
void ffm_kernel(const float* __restrict__ x,
                const float* __restrict__ fe,
                float* __restrict__ out) {
    extern __shared__ float4 sm4[];
    float4* xs4   = sm4;
    float4* stage = sm4 + X_F4;

    const int tid  = threadIdx.x;
    const int warp = tid >> 5;
    const int lane = tid & 31;
    const int word = lane & 15;
    const int sel  = lane >> 4;          // which of the 2 pairs in an iter

    const int half  = blockIdx.x & 1;
    const int pbase = half * NPH + warp * PPW;

    // ---- per-thread precompute: inter in registers + xs offsets ----
    float4  interReg[ITERS];
    unsigned offs[ITERS];                // (i_f4idx << 16) | j_f4idx into xs4
    {
        int i = 0, rem = pbase;
        while (rem >= NF - 1 - i) { rem -= NF - 1 - i; ++i; }
        int j = i + 1 + rem;
        int pi[PPW], pj[PPW];
        #pragma unroll
        for (int p = 0; p < PPW; ++p) {
            pi[p] = i; pj[p] = j;
            if (++j == NF) { ++i; j = i + 1; }
        }
        const float4* fe4 = (const float4*)fe;
        #pragma unroll
        for (int k = 0; k < ITERS; ++k) {
            int ii = pi[2*k + sel], jj = pj[2*k + sel];
            offs[k] = ((unsigned)(ii*16 + word) << 16) | (unsigned)(jj*16 + word);
            float4 a = fe4[(size_t)(ii*NF + jj)*16 + word];
            float4 b = fe4[(size_t)(jj*NF + ii)*16 + word];
            interReg[k] = make_float4(a.x*b.x, a.y*b.y, a.z*b.z, a.w*b.w);
        }
    }

    float4* mybufs = stage + (size_t)warp * (BUFS * BUF_F4);
    const uint32_t sbase = (uint32_t)__cvta_generic_to_shared(mybufs);

    // ---- persistent batch loop, register-prefetched x ----
    const float4* xg4 = (const float4*)x;
    const int b0      = blockIdx.x >> 1;
    const int bstride = gridDim.x >> 1;

    float4 r0 = make_float4(0.f,0.f,0.f,0.f), r1 = r0;
    if (b0 < NBATCH) {
        r0 = xg4[(size_t)b0 * X_F4 + tid];
        if (tid < X_F4 - NTH) r1 = xg4[(size_t)b0 * X_F4 + tid + NTH];
    }

    int bufsel = 0;   // cycles 0..BUFS-1 across all chunks, all rows

    for (int b = b0; b < NBATCH; b += bstride) {
        __syncthreads();                 // previous row's xs readers done
        xs4[tid] = r0;
        if (tid < X_F4 - NTH) xs4[tid + NTH] = r1;

        int bn = b + bstride;
        if (bn < NBATCH) {
            r0 = xg4[(size_t)bn * X_F4 + tid];
            if (tid < X_F4 - NTH) r1 = xg4[(size_t)bn * X_F4 + tid + NTH];
        }
        __syncthreads();                 // xs4 ready

        const float4* og4 = (const float4*)out + (size_t)b * ROW_F4
                          + (size_t)half * HROW_F4 + (size_t)warp * WARP_F4;

        #pragma unroll
        for (int c = 0; c < 4; ++c) {
            const int kbeg = c * 4;
            const int ksz  = (c < 3) ? 4 : 3;       // 4+4+4+3 = 15 iters

            // PHASE 1: compute chunk into registers (no staging-buffer dep)
            float4 v[4];
            #pragma unroll
            for (int kk = 0; kk < 4; ++kk) {
                if (kk < ksz) {
                    const int k = kbeg + kk;
                    unsigned o  = offs[k];
                    float4 a  = xs4[o >> 16];
                    float4 cj = xs4[o & 0xffffu];
                    float4 t  = interReg[k];
                    v[kk] = make_float4(a.x*cj.x*t.x,
                                        a.y*cj.y*t.y,
                                        a.z*cj.z*t.z,
                                        a.w*cj.w*t.w);
                }
            }

            // PHASE 2: now (and only now) require the staging buffer free
            if (lane == 0)
                asm volatile("cp.async.bulk.wait_group.read %0;" :: "n"(BUFS-1) : "memory");
            __syncwarp();

            float4* buf = mybufs + bufsel * BUF_F4;
            #pragma unroll
            for (int kk = 0; kk < 4; ++kk)
                if (kk < ksz) buf[kk*32 + lane] = v[kk];

            asm volatile("fence.proxy.async.shared::cta;" ::: "memory");
            __syncwarp();
            if (lane == 0) {
                bulk_store(og4 + kbeg*32,
                           sbase + (uint32_t)(bufsel * BUF_F4 * sizeof(float4)),
                           ksz * 32 * (int)sizeof(float4));
                asm volatile("cp.async.bulk.commit_group;" ::: "memory");
            }
            if (++bufsel == BUFS) bufsel = 0;
        }
    }

    // drain before exit
    if (lane == 0)
        asm volatile("cp.async.bulk.wait_group.read 0;" ::: "memory");
}

extern "C" void kernel_launch(void* const* d_in, const int* in_sizes, int n_in,
                              void* d_out, int out_size) {
    const float* x  = (const float*)d_in[0];   // [B, F, E] float32
    const float* fe = (const float*)d_in[1];   // [F, F, E] float32
    float* out = (float*)d_out;                // [B, P*E] float32

    (void)in_sizes; (void)n_in; (void)out_size;

    cudaFuncSetAttribute(ffm_kernel,
                         cudaFuncAttributeMaxDynamicSharedMemorySize,
                         (int)SMEM_BYTES);

    int dev = 0, sms = 148;
    cudaGetDevice(&dev);
    cudaDeviceGetAttribute(&sms, cudaDevAttrMultiProcessorCount, dev);
    int grid = sms & ~1;                       // even: 2 pair-halves, 1 CTA/SM
    if (grid < 2) grid = 2;

    ffm_kernel<<<grid, NTH, SMEM_BYTES>>>(x, fe, out);
}